// round 15
// baseline (speedup 1.0000x reference)
#include <cuda_runtime.h>
#include <cuda_fp16.h>
#include <cstdint>

#define NN 50000
#define EE 640000
#define HH 128
#define GG 128
#define FN 64
#define FEDGE 16
#define KK 144
#define FLIG 200
#define FPOC 100
#define GBLK ((NN + 7) / 8)
#define NPB 64
#define MBLK ((NN + NPB - 1) / NPB)    // 782
#define KSTEP (KK / 16)                // 9
#define WIMG 9216
#define ASTRB 336
#define OSTR 132

// ---- scratch (referenced ONLY from device code) ----
__device__ int      g_counts[NN];
__device__ int      g_fill[NN];
__device__ int      g_rowptr[NN + 1];
__device__ int      g_src[EE];
__device__ int      g_eid[EE];
__device__ float    g_h0[NN * HH];
__device__ float    g_h1[NN * HH];
__device__ uint32_t g_hh[NN * (HH / 2)];     // fp16 image of current h
__device__ uint32_t g_xh[NN * (FN / 2)];     // fp16 image of x
__device__ uint32_t g_aggh[NN * (KK / 2)];   // A hi image, f16x2, [n][144]
__device__ uint32_t g_aggl[NN * (KK / 2)];   // A lo (residual) image
__device__ uint32_t g_wh[4 * WIMG];          // W fp16, B-fragment-linear
__device__ float    g_pool[GG * HH];

__device__ __forceinline__ uint32_t h2pk(float lo_elem, float hi_elem) {
    uint32_t r; asm("cvt.rn.f16x2.f32 %0, %1, %2;" : "=r"(r) : "f"(hi_elem), "f"(lo_elem)); return r;
}
__device__ __forceinline__ float hhi(float a) { return __half2float(__float2half_rn(a)); }
__device__ __forceinline__ void add4(float4& a, float4 b) {
    a.x += b.x; a.y += b.y; a.z += b.z; a.w += b.w;
}
__device__ __forceinline__ void addh2(float4& a, uint32_t w0, uint32_t w1) {
    float2 p0 = __half22float2(*(const __half2*)&w0);
    float2 p1 = __half22float2(*(const __half2*)&w1);
    a.x += p0.x; a.y += p0.y; a.z += p1.x; a.w += p1.y;
}
__device__ __forceinline__ void cvt_hl(float4 v, uint32_t* hi, uint32_t* lo) {
    float hx = hhi(v.x), hy = hhi(v.y), hz = hhi(v.z), hw = hhi(v.w);
    hi[0] = h2pk(v.x, v.y); hi[1] = h2pk(v.z, v.w);
    lo[0] = h2pk(v.x - hx, v.y - hy); lo[1] = h2pk(v.z - hz, v.w - hw);
}
__device__ __forceinline__ void red8(float4& p, float4& q, int m) {
    p.x += __shfl_xor_sync(0xffffffffu, p.x, m);
    p.y += __shfl_xor_sync(0xffffffffu, p.y, m);
    p.z += __shfl_xor_sync(0xffffffffu, p.z, m);
    p.w += __shfl_xor_sync(0xffffffffu, p.w, m);
    q.x += __shfl_xor_sync(0xffffffffu, q.x, m);
    q.y += __shfl_xor_sync(0xffffffffu, q.y, m);
    q.z += __shfl_xor_sync(0xffffffffu, q.z, m);
    q.w += __shfl_xor_sync(0xffffffffu, q.w, m);
}
__device__ __forceinline__ void mma16816(float* c, const uint32_t* a, uint2 b) {
    asm("mma.sync.aligned.m16n8k16.row.col.f32.f16.f16.f32 "
        "{%0,%1,%2,%3}, {%4,%5,%6,%7}, {%8,%9}, {%0,%1,%2,%3};"
        : "+f"(c[0]), "+f"(c[1]), "+f"(c[2]), "+f"(c[3])
        : "r"(a[0]), "r"(a[1]), "r"(a[2]), "r"(a[3]), "r"(b.x), "r"(b.y));
}
__device__ __forceinline__ int lbound(const int* __restrict__ arr, int n, int v) {
    int lo = 0, hi = n;
    while (lo < hi) { int m = (lo + hi) >> 1; if (arr[m] < v) lo = m + 1; else hi = m; }
    return lo;
}

// ---- x -> fp16 image ----
__global__ void k_xconv(const float* __restrict__ x) {
    int id = blockIdx.x * blockDim.x + threadIdx.x;
    if (id >= NN * (FN / 2)) return;
    float2 v = ((const float2*)x)[id];
    g_xh[id] = h2pk(v.x, v.y);
}

// ---- CSR build ----
__global__ void k_count(const int* __restrict__ ei) {
    int t = blockIdx.x * blockDim.x + threadIdx.x;
    if (t >= EE / 4) return;
    int4 d = ((const int4*)(ei + EE))[t];
    atomicAdd(&g_counts[d.x], 1);
    atomicAdd(&g_counts[d.y], 1);
    atomicAdd(&g_counts[d.z], 1);
    atomicAdd(&g_counts[d.w], 1);
}

__global__ void k_scan() {
    __shared__ int ss[1024];
    int t = threadIdx.x;
    const int chunk = (NN + 1023) / 1024;
    int start = t * chunk, end = min(start + chunk, NN);
    int s = 0;
    for (int i = start; i < end; i++) s += g_counts[i];
    ss[t] = s;
    __syncthreads();
    for (int off = 1; off < 1024; off <<= 1) {
        int v = (t >= off) ? ss[t - off] : 0;
        __syncthreads();
        ss[t] += v;
        __syncthreads();
    }
    int run = (t == 0) ? 0 : ss[t - 1];
    for (int i = start; i < end; i++) { g_rowptr[i] = run; run += g_counts[i]; }
    if (t == 1023) g_rowptr[NN] = ss[1023];
}

// scalar: one edge per thread (max warps for latency hiding)
__global__ void k_fill(const int* __restrict__ ei) {
    int e = blockIdx.x * blockDim.x + threadIdx.x;
    if (e >= EE) return;
    int d = ei[EE + e];
    int p = g_rowptr[d] + atomicAdd(&g_fill[d], 1);
    g_src[p] = ei[e];
    g_eid[p] = e;
    g_counts[d] = 0;
}

// ---- W image (fp16) in mma-B-fragment-linear order ----
__global__ void k_wconv(const float* __restrict__ W1m, const float* __restrict__ W1s,
                        const float* __restrict__ W1e, const float* __restrict__ Wkm,
                        const float* __restrict__ Wke) {
    int id = blockIdx.x * blockDim.x + threadIdx.x;
    if (id >= 4 * WIMG) return;
    int L = id / WIMG, r = id % WIMG;
    int s = r / 1024, r2 = r % 1024;
    int nb = r2 / 64, q = r2 % 64;
    int lane = q >> 1, reg = q & 1;
    int k = s * 16 + reg * 8 + (lane & 3) * 2;
    int n = nb * 8 + (lane >> 2);
    float a, b;
    if (L == 0) {
        if (k < 64)       { a = W1m[k * 128 + n];         b = W1m[(k + 1) * 128 + n]; }
        else if (k < 128) { a = W1s[(k - 64) * 128 + n];  b = W1s[(k - 63) * 128 + n]; }
        else              { a = W1e[(k - 128) * 128 + n]; b = W1e[(k - 127) * 128 + n]; }
    } else {
        int l = L - 1;
        if (k < 128) { a = Wkm[l * 16384 + k * 128 + n];         b = Wkm[l * 16384 + (k + 1) * 128 + n]; }
        else         { a = Wke[l * 2048 + (k - 128) * 128 + n];  b = Wke[l * 2048 + (k - 127) * 128 + n]; }
    }
    g_wh[id] = h2pk(a, b);
}

// ---- gather conv1: quarter-warp per edge (8 lanes x uint4 = 128B x-row) ----
__global__ void __launch_bounds__(256) k_gather1(const float* __restrict__ ea) {
    int warp = threadIdx.x >> 5, lane = threadIdx.x & 31;
    int n = blockIdx.x * 8 + warp;
    if (n >= NN) return;
    int beg = g_rowptr[n], end = g_rowptr[n + 1];
    int q8 = lane >> 3, l8 = lane & 7, q = lane & 3;
    const uint4* xb4 = (const uint4*)g_xh;   // 8 uint4 per x-row

    float4 p0 = make_float4(0.f, 0.f, 0.f, 0.f), q0 = p0, p1 = p0, q1 = p0;
    int s = beg;
    for (; s + 7 < end; s += 8) {
        uint4 w0 = xb4[g_src[s + q8] * 8 + l8];
        uint4 w1 = xb4[g_src[s + 4 + q8] * 8 + l8];
        addh2(p0, w0.x, w0.y); addh2(q0, w0.z, w0.w);
        addh2(p1, w1.x, w1.y); addh2(q1, w1.z, w1.w);
    }
    for (; s + 3 < end; s += 4) {
        uint4 w = xb4[g_src[s + q8] * 8 + l8];
        addh2(p0, w.x, w.y); addh2(q0, w.z, w.w);
    }
    int rem = end - s;
    if (q8 < rem) {
        uint4 w = xb4[g_src[s + q8] * 8 + l8];
        addh2(p0, w.x, w.y); addh2(q0, w.z, w.w);
    }
    add4(p0, p1); add4(q0, q1);
    red8(p0, q0, 8);
    red8(p0, q0, 16);
    uint32_t hi[4], lo[4];
    if (lane < 8) {           // ax -> words 0..31
        cvt_hl(p0, hi, lo);
        cvt_hl(q0, hi + 2, lo + 2);
        *(uint4*)&g_aggh[n * 72 + l8 * 4] = make_uint4(hi[0], hi[1], hi[2], hi[3]);
        *(uint4*)&g_aggl[n * 72 + l8 * 4] = make_uint4(lo[0], lo[1], lo[2], lo[3]);
    } else if (lane < 16) {   // x self -> words 32..63
        uint4 w = xb4[n * 8 + l8];
        float4 pp = make_float4(0.f, 0.f, 0.f, 0.f), qq = pp;
        addh2(pp, w.x, w.y); addh2(qq, w.z, w.w);
        cvt_hl(pp, hi, lo);
        cvt_hl(qq, hi + 2, lo + 2);
        *(uint4*)&g_aggh[n * 72 + 32 + l8 * 4] = make_uint4(hi[0], hi[1], hi[2], hi[3]);
        *(uint4*)&g_aggl[n * 72 + 32 + l8 * 4] = make_uint4(lo[0], lo[1], lo[2], lo[3]);
    }

    // ae: 8 edges per step (fp32 edge_attr)
    float4 ac = make_float4(0.f, 0.f, 0.f, 0.f);
    for (int t2 = beg; t2 < end; t2 += 8) {
        int e = t2 + (lane >> 2);
        if (e < end) add4(ac, ((const float4*)ea)[g_eid[e] * 4 + q]);
    }
    #pragma unroll
    for (int m = 4; m <= 16; m <<= 1) {
        ac.x += __shfl_xor_sync(0xffffffffu, ac.x, m);
        ac.y += __shfl_xor_sync(0xffffffffu, ac.y, m);
        ac.z += __shfl_xor_sync(0xffffffffu, ac.z, m);
        ac.w += __shfl_xor_sync(0xffffffffu, ac.w, m);
    }
    if (lane < 4) {           // ae -> words 64..71
        cvt_hl(ac, hi, lo);
        *(uint2*)&g_aggh[n * 72 + 64 + 2 * q] = make_uint2(hi[0], hi[1]);
        *(uint2*)&g_aggl[n * 72 + 64 + 2 * q] = make_uint2(lo[0], lo[1]);
    }
    if (lane == 24) g_fill[n] = 0;
}

// ---- gather layers: half-warp per edge (16 lanes x uint4 = 256B h-row) ----
__global__ void __launch_bounds__(256) k_gatherL(int l) {
    int warp = threadIdx.x >> 5, lane = threadIdx.x & 31;
    int n = blockIdx.x * 8 + warp;
    if (n >= NN) return;
    int beg = g_rowptr[n], end = g_rowptr[n + 1];
    int half = lane >> 4, hl = lane & 15;
    const uint4* hb = (const uint4*)g_hh;   // 16 uint4 per h-row

    float4 p0 = make_float4(0.f, 0.f, 0.f, 0.f), q0 = p0;
    float4 p1 = p0, q1 = p0, p2 = p0, q2 = p0, p3 = p0, q3 = p0;
    int s = beg;
    for (; s + 7 < end; s += 8) {
        uint4 w0 = hb[g_src[s + half] * 16 + hl];
        uint4 w1 = hb[g_src[s + 2 + half] * 16 + hl];
        uint4 w2 = hb[g_src[s + 4 + half] * 16 + hl];
        uint4 w3 = hb[g_src[s + 6 + half] * 16 + hl];
        addh2(p0, w0.x, w0.y); addh2(q0, w0.z, w0.w);
        addh2(p1, w1.x, w1.y); addh2(q1, w1.z, w1.w);
        addh2(p2, w2.x, w2.y); addh2(q2, w2.z, w2.w);
        addh2(p3, w3.x, w3.y); addh2(q3, w3.z, w3.w);
    }
    for (; s + 1 < end; s += 2) {
        uint4 w = hb[g_src[s + half] * 16 + hl];
        addh2(p0, w.x, w.y); addh2(q0, w.z, w.w);
    }
    if (s < end && half == 0) {
        uint4 w = hb[g_src[s] * 16 + hl];
        addh2(p0, w.x, w.y); addh2(q0, w.z, w.w);
    }
    add4(p0, p1); add4(q0, q1); add4(p2, p3); add4(q2, q3);
    add4(p0, p2); add4(q0, q2);
    red8(p0, q0, 16);
    if (half == 0) {
        uint32_t hi[4], lo[4];
        cvt_hl(p0, hi, lo);
        cvt_hl(q0, hi + 2, lo + 2);
        *(uint4*)&g_aggh[n * 72 + hl * 4] = make_uint4(hi[0], hi[1], hi[2], hi[3]);
        *(uint4*)&g_aggl[n * 72 + hl * 4] = make_uint4(lo[0], lo[1], lo[2], lo[3]);
    }
}

// ---- split-fp16 mma.sync GEMM: out[64,128] = A[64,144] @ W[144,128] + epilogue ----
__global__ void __launch_bounds__(256) k_gemm(int l,
        const float* __restrict__ bmv, const float* __restrict__ bev,
        const float* __restrict__ bsv) {
    const uint32_t* __restrict__ wh = g_wh + (l + 1) * WIMG;
    const float* __restrict__ hself = (l < 0) ? nullptr : ((l & 1) ? g_h1 : g_h0);
    float* __restrict__ hout = (l < 0) ? g_h0 : ((l & 1) ? g_h0 : g_h1);

    __shared__ __align__(16) unsigned char smbuf[2 * NPB * ASTRB];
    __shared__ float bb[128], bsl[128], sdeg[NPB];
    unsigned char* Ahi = smbuf;
    unsigned char* Alo = smbuf + NPB * ASTRB;
    int tid = threadIdx.x;
    int n0 = blockIdx.x * NPB;

    for (int idx = tid; idx < NPB * 18; idx += 256) {
        int row = idx / 18, c = idx % 18;
        int node = min(n0 + row, NN - 1);
        *(uint4*)(Ahi + row * ASTRB + c * 16) = *(const uint4*)&g_aggh[node * 72 + c * 4];
        *(uint4*)(Alo + row * ASTRB + c * 16) = *(const uint4*)&g_aggl[node * 72 + c * 4];
    }
    if (tid < 128) {
        bb[tid] = bmv[tid] + bev[tid];
        bsl[tid] = bsv ? bsv[tid] : 0.f;
    } else if (tid < 128 + NPB) {
        int node = min(n0 + tid - 128, NN - 1);
        sdeg[tid - 128] = (float)(g_rowptr[node + 1] - g_rowptr[node]);
    }
    __syncthreads();

    int wid = tid >> 5, lane = tid & 31;
    int wm = wid & 3, wn = wid >> 2;
    int rowbase = wm * 16, colbase = wn * 64;
    int lq = lane >> 2, lr = lane & 3;

    float acc[8][4];
    #pragma unroll
    for (int nf = 0; nf < 8; nf++)
        #pragma unroll
        for (int c = 0; c < 4; c++) acc[nf][c] = 0.f;

    #pragma unroll 1
    for (int pass = 0; pass < 2; pass++) {
        const unsigned char* Ash = pass ? Alo : Ahi;
        #pragma unroll 1
        for (int s = 0; s < KSTEP; s++) {
            uint32_t a[4];
            const unsigned char* base = Ash + (rowbase + lq) * ASTRB + (s * 16 + lr * 2) * 2;
            a[0] = *(const uint32_t*)(base);
            a[1] = *(const uint32_t*)(base + 8 * ASTRB);
            a[2] = *(const uint32_t*)(base + 16);
            a[3] = *(const uint32_t*)(base + 8 * ASTRB + 16);
            #pragma unroll
            for (int nf = 0; nf < 8; nf++) {
                uint2 b = *(const uint2*)&wh[(s * 16 + wn * 8 + nf) * 64 + lane * 2];
                mma16816(acc[nf], a, b);
            }
        }
    }

    float selfv[8][4];
    #pragma unroll
    for (int nf = 0; nf < 8; nf++) {
        int col = colbase + nf * 8 + lr * 2;
        #pragma unroll
        for (int h = 0; h < 2; h++) {
            int n = n0 + rowbase + lq + h * 8;
            int nc = min(n, NN - 1);
            if (hself) {
                float2 sv = *(const float2*)&hself[nc * HH + col];
                selfv[nf][2 * h] = sv.x; selfv[nf][2 * h + 1] = sv.y;
            } else {
                selfv[nf][2 * h] = bsl[col]; selfv[nf][2 * h + 1] = bsl[col + 1];
            }
        }
    }
    __syncthreads();
    float* stage = (float*)smbuf;
    #pragma unroll
    for (int nf = 0; nf < 8; nf++) {
        int col = colbase + nf * 8 + lr * 2;
        float bc0 = bb[col], bc1 = bb[col + 1];
        #pragma unroll
        for (int h = 0; h < 2; h++) {
            int rl = rowbase + lq + h * 8;
            float dg = sdeg[rl];
            float2 o;
            o.x = fmaxf(acc[nf][2 * h]     + dg * bc0 + selfv[nf][2 * h], 0.f);
            o.y = fmaxf(acc[nf][2 * h + 1] + dg * bc1 + selfv[nf][2 * h + 1], 0.f);
            *(float2*)&stage[rl * OSTR + col] = o;
        }
    }
    __syncthreads();
    bool emit16 = (l < 2);
    #pragma unroll
    for (int i = 0; i < 8; i++) {
        int idx = i * 256 + tid;
        int row = idx >> 5, c4 = idx & 31;
        int n = n0 + row;
        if (n < NN) {
            float4 v = *(const float4*)&stage[row * OSTR + c4 * 4];
            *(float4*)&hout[n * HH + c4 * 4] = v;
            if (emit16)
                *(uint2*)&g_hh[n * 64 + c4 * 2] = make_uint2(h2pk(v.x, v.y), h2pk(v.z, v.w));
        }
    }
}

// ---- mean pool ----
__global__ void __launch_bounds__(256) k_pool(const int* __restrict__ batch) {
    int g = blockIdx.x;
    int tid = threadIdx.x;
    int j = tid & 127, half = tid >> 7;
    int lo = lbound(batch, NN, g);
    int hi = lbound(batch, NN, g + 1);
    float a = 0.f, b = 0.f;
    int n = lo + half;
    for (; n + 3 < hi; n += 4) {
        a += g_h1[n * HH + j];
        b += g_h1[(n + 2) * HH + j];
    }
    for (; n < hi; n += 2) a += g_h1[n * HH + j];
    __shared__ float red[256];
    red[tid] = a + b;
    __syncthreads();
    if (half == 0) {
        float s = red[j] + red[j + 128];
        float c = (float)(hi - lo);
        g_pool[g * HH + j] = s / fmaxf(c, 1.f);
    }
}

// ---- head ----
__global__ void k_head(const float* __restrict__ lig, const float* __restrict__ poc,
                       const float* __restrict__ Wl, const float* __restrict__ bl,
                       const float* __restrict__ Wp, const float* __restrict__ bp,
                       const float* __restrict__ Wf, const float* __restrict__ bf,
                       const float* __restrict__ Wo, const float* __restrict__ bo,
                       float* __restrict__ out) {
    int g = blockIdx.x, j = threadIdx.x;
    __shared__ float f[3 * HH];
    __shared__ float o[HH];
    f[j] = g_pool[g * HH + j];
    float a = bl[j];
    #pragma unroll 4
    for (int k = 0; k < FLIG; k++) a += lig[g * FLIG + k] * Wl[k * HH + j];
    f[HH + j] = a;
    float b = bp[j];
    #pragma unroll 4
    for (int k = 0; k < FPOC; k++) b += poc[g * FPOC + k] * Wp[k * HH + j];
    f[2 * HH + j] = b;
    __syncthreads();
    float acc = bf[j];
    #pragma unroll 8
    for (int k = 0; k < 3 * HH; k++) acc += f[k] * Wf[k * HH + j];
    o[j] = acc * Wo[j];
    __syncthreads();
    for (int s = 64; s > 0; s >>= 1) {
        if (j < s) o[j] += o[j + s];
        __syncthreads();
    }
    if (j == 0) out[g] = o[0] + bo[0];
}

extern "C" void kernel_launch(void* const* d_in, const int* in_sizes, int n_in,
                              void* d_out, int out_size) {
    const float* x    = (const float*)d_in[0];
    const int*   ei   = (const int*)d_in[1];
    const float* ea   = (const float*)d_in[2];
    const int*   batch= (const int*)d_in[3];
    const float* lig  = (const float*)d_in[4];
    const float* poc  = (const float*)d_in[5];
    const float* W1m  = (const float*)d_in[6];
    const float* b1m  = (const float*)d_in[7];
    const float* W1e  = (const float*)d_in[8];
    const float* b1e  = (const float*)d_in[9];
    const float* W1s  = (const float*)d_in[10];
    const float* b1s  = (const float*)d_in[11];
    const float* Wkm  = (const float*)d_in[12];
    const float* bkm  = (const float*)d_in[13];
    const float* Wke  = (const float*)d_in[14];
    const float* bke  = (const float*)d_in[15];
    const float* Wl   = (const float*)d_in[16];
    const float* bl   = (const float*)d_in[17];
    const float* Wp   = (const float*)d_in[18];
    const float* bp   = (const float*)d_in[19];
    const float* Wf   = (const float*)d_in[20];
    const float* bf   = (const float*)d_in[21];
    const float* Wo   = (const float*)d_in[22];
    const float* bo   = (const float*)d_in[23];
    float* out = (float*)d_out;

    k_xconv  <<<(NN * (FN / 2) + 255) / 256, 256>>>(x);                 // 0
    k_count  <<<(EE / 4 + 255) / 256, 256>>>(ei);                       // 1
    k_scan   <<<1, 1024>>>();                                           // 2
    k_fill   <<<(EE + 255) / 256, 256>>>(ei);                           // 3 (profiled)
    k_wconv  <<<(4 * WIMG + 255) / 256, 256>>>(W1m, W1s, W1e, Wkm, Wke);// 4
    k_gather1<<<GBLK, 256>>>(ea);                                       // 5
    k_gemm   <<<MBLK, 256>>>(-1, b1m, b1e, b1s);                        // 6
    for (int l = 0; l < 3; l++) {
        k_gatherL<<<GBLK, 256>>>(l);
        k_gemm   <<<MBLK, 256>>>(l, bkm + l * HH, bke + l * HH, nullptr);
    }
    k_pool <<<GG, 256>>>(batch);
    k_head <<<GG, HH>>>(lig, poc, Wl, bl, Wp, bp, Wf, bf, Wo, bo, out);
}

// round 17
// speedup vs baseline: 1.1306x; 1.1306x over previous
#include <cuda_runtime.h>
#include <cuda_fp16.h>
#include <cstdint>

#define NN 50000
#define EE 640000
#define HH 128
#define GG 128
#define FN 64
#define FEDGE 16
#define KK 144
#define FLIG 200
#define FPOC 100
#define GBLK ((NN + 7) / 8)
#define NPB 64
#define MBLK ((NN + NPB - 1) / NPB)    // 782
#define KSTEP (KK / 16)                // 9
#define WIMG 9216
#define ASTRB 336
#define OSTR 132

// ---- scratch (referenced ONLY from device code) ----
__device__ int      g_counts[NN];
__device__ int      g_fill[NN];
__device__ int      g_rowptr[NN + 1];
__device__ int      g_src[EE];
__device__ int      g_eid[EE];
__device__ float    g_h0[NN * HH];
__device__ float    g_h1[NN * HH];
__device__ uint32_t g_hh[NN * (HH / 2)];     // fp16 image of current h
__device__ uint32_t g_xh[NN * (FN / 2)];     // fp16 image of x
__device__ uint32_t g_aggh[NN * (KK / 2)];   // A hi image, f16x2, [n][144]
__device__ uint32_t g_aggl[NN * (KK / 2)];   // A lo (residual) image
__device__ uint32_t g_wh[4 * WIMG];          // W fp16, B-fragment-linear
__device__ float    g_pool[GG * HH];

__device__ __forceinline__ uint32_t h2pk(float lo_elem, float hi_elem) {
    uint32_t r; asm("cvt.rn.f16x2.f32 %0, %1, %2;" : "=r"(r) : "f"(hi_elem), "f"(lo_elem)); return r;
}
__device__ __forceinline__ float hhi(float a) { return __half2float(__float2half_rn(a)); }
__device__ __forceinline__ void add4(float4& a, float4 b) {
    a.x += b.x; a.y += b.y; a.z += b.z; a.w += b.w;
}
__device__ __forceinline__ void addh2(float4& a, uint2 w) {
    float2 p0 = __half22float2(*(const __half2*)&w.x);
    float2 p1 = __half22float2(*(const __half2*)&w.y);
    a.x += p0.x; a.y += p0.y; a.z += p1.x; a.w += p1.y;
}
__device__ __forceinline__ void cvt_hl(float4 v, uint32_t* hi, uint32_t* lo) {
    float hx = hhi(v.x), hy = hhi(v.y), hz = hhi(v.z), hw = hhi(v.w);
    hi[0] = h2pk(v.x, v.y); hi[1] = h2pk(v.z, v.w);
    lo[0] = h2pk(v.x - hx, v.y - hy); lo[1] = h2pk(v.z - hz, v.w - hw);
}
__device__ __forceinline__ void mma16816(float* c, const uint32_t* a, uint2 b) {
    asm("mma.sync.aligned.m16n8k16.row.col.f32.f16.f16.f32 "
        "{%0,%1,%2,%3}, {%4,%5,%6,%7}, {%8,%9}, {%0,%1,%2,%3};"
        : "+f"(c[0]), "+f"(c[1]), "+f"(c[2]), "+f"(c[3])
        : "r"(a[0]), "r"(a[1]), "r"(a[2]), "r"(a[3]), "r"(b.x), "r"(b.y));
}
__device__ __forceinline__ int lbound(const int* __restrict__ arr, int n, int v) {
    int lo = 0, hi = n;
    while (lo < hi) { int m = (lo + hi) >> 1; if (arr[m] < v) lo = m + 1; else hi = m; }
    return lo;
}

// ---- CSR count + x->fp16 image (merged) ----
__global__ void k_count(const int* __restrict__ ei, const float* __restrict__ x) {
    int t = blockIdx.x * blockDim.x + threadIdx.x;
    if (t < EE / 4) {
        int4 d = ((const int4*)(ei + EE))[t];
        atomicAdd(&g_counts[d.x], 1);
        atomicAdd(&g_counts[d.y], 1);
        atomicAdd(&g_counts[d.z], 1);
        atomicAdd(&g_counts[d.w], 1);
    }
    if (t < NN * (FN / 2)) {
        float2 v = ((const float2*)x)[t];
        g_xh[t] = h2pk(v.x, v.y);
    }
}

__global__ void k_scan() {
    __shared__ int ss[1024];
    int t = threadIdx.x;
    const int chunk = (NN + 1023) / 1024;
    int start = t * chunk, end = min(start + chunk, NN);
    int s = 0;
    for (int i = start; i < end; i++) s += g_counts[i];
    ss[t] = s;
    __syncthreads();
    for (int off = 1; off < 1024; off <<= 1) {
        int v = (t >= off) ? ss[t - off] : 0;
        __syncthreads();
        ss[t] += v;
        __syncthreads();
    }
    int run = (t == 0) ? 0 : ss[t - 1];
    for (int i = start; i < end; i++) { g_rowptr[i] = run; run += g_counts[i]; }
    if (t == 1023) g_rowptr[NN] = ss[1023];
}

// scalar: one edge per thread (max warps for latency hiding); resets g_counts
__global__ void k_fill(const int* __restrict__ ei) {
    int e = blockIdx.x * blockDim.x + threadIdx.x;
    if (e >= EE) return;
    int d = ei[EE + e];
    int p = g_rowptr[d] + atomicAdd(&g_fill[d], 1);
    g_src[p] = ei[e];
    g_eid[p] = e;
    g_counts[d] = 0;
}

// ---- W image (fp16) in mma-B-fragment-linear order ----
__global__ void k_wconv(const float* __restrict__ W1m, const float* __restrict__ W1s,
                        const float* __restrict__ W1e, const float* __restrict__ Wkm,
                        const float* __restrict__ Wke) {
    int id = blockIdx.x * blockDim.x + threadIdx.x;
    if (id >= 4 * WIMG) return;
    int L = id / WIMG, r = id % WIMG;
    int s = r / 1024, r2 = r % 1024;
    int nb = r2 / 64, q = r2 % 64;
    int lane = q >> 1, reg = q & 1;
    int k = s * 16 + reg * 8 + (lane & 3) * 2;
    int n = nb * 8 + (lane >> 2);
    float a, b;
    if (L == 0) {
        if (k < 64)       { a = W1m[k * 128 + n];         b = W1m[(k + 1) * 128 + n]; }
        else if (k < 128) { a = W1s[(k - 64) * 128 + n];  b = W1s[(k - 63) * 128 + n]; }
        else              { a = W1e[(k - 128) * 128 + n]; b = W1e[(k - 127) * 128 + n]; }
    } else {
        int l = L - 1;
        if (k < 128) { a = Wkm[l * 16384 + k * 128 + n];         b = Wkm[l * 16384 + (k + 1) * 128 + n]; }
        else         { a = Wke[l * 2048 + (k - 128) * 128 + n];  b = Wke[l * 2048 + (k - 127) * 128 + n]; }
    }
    g_wh[id] = h2pk(a, b);
}

// ---- gather conv1 (R13 form): [ax | x | ae] -> f16 hi/lo images ----
__global__ void __launch_bounds__(256) k_gather1(const float* __restrict__ ea) {
    int warp = threadIdx.x >> 5, lane = threadIdx.x & 31;
    int n = blockIdx.x * 8 + warp;
    if (n >= NN) return;
    int beg = g_rowptr[n], end = g_rowptr[n + 1];
    int half = lane >> 4, hl = lane & 15, q = lane & 3;

    float4 a0 = make_float4(0.f, 0.f, 0.f, 0.f), a1 = a0;
    int s = beg;
    for (; s + 3 < end; s += 4) {
        addh2(a0, *(const uint2*)&g_xh[g_src[s + half] * 32 + hl * 2]);
        addh2(a1, *(const uint2*)&g_xh[g_src[s + 2 + half] * 32 + hl * 2]);
    }
    for (; s + 1 < end; s += 2) addh2(a0, *(const uint2*)&g_xh[g_src[s + half] * 32 + hl * 2]);
    if (s < end && half == 0) addh2(a0, *(const uint2*)&g_xh[g_src[s] * 32 + hl * 2]);
    add4(a0, a1);
    a0.x += __shfl_xor_sync(0xffffffffu, a0.x, 16);
    a0.y += __shfl_xor_sync(0xffffffffu, a0.y, 16);
    a0.z += __shfl_xor_sync(0xffffffffu, a0.z, 16);
    a0.w += __shfl_xor_sync(0xffffffffu, a0.w, 16);
    uint32_t hi[2], lo[2];
    if (half == 0) {
        cvt_hl(a0, hi, lo);
        *(uint2*)&g_aggh[n * 72 + 2 * hl] = make_uint2(hi[0], hi[1]);
        *(uint2*)&g_aggl[n * 72 + 2 * hl] = make_uint2(lo[0], lo[1]);
    } else {
        float4 v = make_float4(0.f, 0.f, 0.f, 0.f);
        addh2(v, *(const uint2*)&g_xh[n * 32 + hl * 2]);
        cvt_hl(v, hi, lo);
        *(uint2*)&g_aggh[n * 72 + 32 + 2 * hl] = make_uint2(hi[0], hi[1]);
        *(uint2*)&g_aggl[n * 72 + 32 + 2 * hl] = make_uint2(lo[0], lo[1]);
    }

    float4 ac = make_float4(0.f, 0.f, 0.f, 0.f);
    for (int t2 = beg; t2 < end; t2 += 8) {
        int e = t2 + (lane >> 2);
        if (e < end) add4(ac, ((const float4*)ea)[g_eid[e] * 4 + q]);
    }
    #pragma unroll
    for (int m = 4; m <= 16; m <<= 1) {
        ac.x += __shfl_xor_sync(0xffffffffu, ac.x, m);
        ac.y += __shfl_xor_sync(0xffffffffu, ac.y, m);
        ac.z += __shfl_xor_sync(0xffffffffu, ac.z, m);
        ac.w += __shfl_xor_sync(0xffffffffu, ac.w, m);
    }
    if (lane < 4) {
        cvt_hl(ac, hi, lo);
        *(uint2*)&g_aggh[n * 72 + 64 + 2 * q] = make_uint2(hi[0], hi[1]);
        *(uint2*)&g_aggl[n * 72 + 64 + 2 * q] = make_uint2(lo[0], lo[1]);
    }
    if (lane == 8) g_fill[n] = 0;
}

// ---- gather layers (R13 form): ah from fp16 h image; 8-deep unroll ----
__global__ void __launch_bounds__(256) k_gatherL(int l) {
    int warp = threadIdx.x >> 5, lane = threadIdx.x & 31;
    int n = blockIdx.x * 8 + warp;
    if (n >= NN) return;
    int beg = g_rowptr[n], end = g_rowptr[n + 1];
    float4 a0 = make_float4(0.f, 0.f, 0.f, 0.f), a1 = a0, a2 = a0, a3 = a0;
    float4 a4 = a0, a5 = a0, a6 = a0, a7 = a0;
    int w2 = lane * 2;
    int s = beg;
    for (; s + 7 < end; s += 8) {
        addh2(a0, *(const uint2*)&g_hh[g_src[s] * 64 + w2]);
        addh2(a1, *(const uint2*)&g_hh[g_src[s + 1] * 64 + w2]);
        addh2(a2, *(const uint2*)&g_hh[g_src[s + 2] * 64 + w2]);
        addh2(a3, *(const uint2*)&g_hh[g_src[s + 3] * 64 + w2]);
        addh2(a4, *(const uint2*)&g_hh[g_src[s + 4] * 64 + w2]);
        addh2(a5, *(const uint2*)&g_hh[g_src[s + 5] * 64 + w2]);
        addh2(a6, *(const uint2*)&g_hh[g_src[s + 6] * 64 + w2]);
        addh2(a7, *(const uint2*)&g_hh[g_src[s + 7] * 64 + w2]);
    }
    for (; s + 1 < end; s += 2) {
        addh2(a0, *(const uint2*)&g_hh[g_src[s] * 64 + w2]);
        addh2(a1, *(const uint2*)&g_hh[g_src[s + 1] * 64 + w2]);
    }
    for (; s < end; s++) addh2(a0, *(const uint2*)&g_hh[g_src[s] * 64 + w2]);
    add4(a0, a1); add4(a2, a3); add4(a4, a5); add4(a6, a7);
    add4(a0, a2); add4(a4, a6); add4(a0, a4);
    uint32_t hi[2], lo[2];
    cvt_hl(a0, hi, lo);
    *(uint2*)&g_aggh[n * 72 + 2 * lane] = make_uint2(hi[0], hi[1]);
    *(uint2*)&g_aggl[n * 72 + 2 * lane] = make_uint2(lo[0], lo[1]);
}

// ---- split-fp16 mma.sync GEMM, B-reuse layout: 4 warps, warp tile 32x64 ----
__global__ void __launch_bounds__(128) k_gemm(int l,
        const float* __restrict__ bmv, const float* __restrict__ bev,
        const float* __restrict__ bsv) {
    const uint32_t* __restrict__ wh = g_wh + (l + 1) * WIMG;
    const float* __restrict__ hself = (l < 0) ? nullptr : ((l & 1) ? g_h1 : g_h0);
    float* __restrict__ hout = (l < 0) ? g_h0 : ((l & 1) ? g_h0 : g_h1);

    __shared__ __align__(16) unsigned char smbuf[2 * NPB * ASTRB];
    __shared__ float bb[128], bsl[128], sdeg[NPB];
    unsigned char* Ahi = smbuf;
    unsigned char* Alo = smbuf + NPB * ASTRB;
    int tid = threadIdx.x;
    int n0 = blockIdx.x * NPB;

    for (int idx = tid; idx < NPB * 18; idx += 128) {
        int row = idx / 18, c = idx % 18;
        int node = min(n0 + row, NN - 1);
        *(uint4*)(Ahi + row * ASTRB + c * 16) = *(const uint4*)&g_aggh[node * 72 + c * 4];
        *(uint4*)(Alo + row * ASTRB + c * 16) = *(const uint4*)&g_aggl[node * 72 + c * 4];
    }
    bb[tid] = bmv[tid] + bev[tid];
    bsl[tid] = bsv ? bsv[tid] : 0.f;
    if (tid < NPB) {
        int node = min(n0 + tid, NN - 1);
        sdeg[tid] = (float)(g_rowptr[node + 1] - g_rowptr[node]);
    }
    __syncthreads();

    int wid = tid >> 5, lane = tid & 31;
    int wm = wid & 1, wn = wid >> 1;          // 2 row-groups (32) x 2 col-groups (64)
    int colbase = wn * 64;
    int lq = lane >> 2, lr = lane & 3;

    float acc[2][8][4];
    #pragma unroll
    for (int mf = 0; mf < 2; mf++)
        #pragma unroll
        for (int nf = 0; nf < 8; nf++)
            #pragma unroll
            for (int c = 0; c < 4; c++) acc[mf][nf][c] = 0.f;

    #pragma unroll 1
    for (int s = 0; s < KSTEP; s++) {
        uint2 b[8];
        #pragma unroll
        for (int nf = 0; nf < 8; nf++)
            b[nf] = *(const uint2*)&wh[(s * 16 + wn * 8 + nf) * 64 + lane * 2];
        #pragma unroll
        for (int mf = 0; mf < 2; mf++) {
            int r = wm * 32 + mf * 16 + lq;
            int koff = (s * 16 + lr * 2) * 2;
            uint32_t a[4];
            const unsigned char* ph = Ahi + r * ASTRB + koff;
            a[0] = *(const uint32_t*)(ph);
            a[1] = *(const uint32_t*)(ph + 8 * ASTRB);
            a[2] = *(const uint32_t*)(ph + 16);
            a[3] = *(const uint32_t*)(ph + 8 * ASTRB + 16);
            #pragma unroll
            for (int nf = 0; nf < 8; nf++) mma16816(acc[mf][nf], a, b[nf]);
            const unsigned char* pl = Alo + r * ASTRB + koff;
            a[0] = *(const uint32_t*)(pl);
            a[1] = *(const uint32_t*)(pl + 8 * ASTRB);
            a[2] = *(const uint32_t*)(pl + 16);
            a[3] = *(const uint32_t*)(pl + 8 * ASTRB + 16);
            #pragma unroll
            for (int nf = 0; nf < 8; nf++) mma16816(acc[mf][nf], a, b[nf]);
        }
    }
    __syncthreads();   // done reading Ahi/Alo

    // epilogue: stage relu(D + deg*(bm+be) + self), then coalesced stores
    float* stage = (float*)smbuf;
    #pragma unroll
    for (int mf = 0; mf < 2; mf++) {
        #pragma unroll
        for (int nf = 0; nf < 8; nf++) {
            int col = colbase + nf * 8 + lr * 2;
            float bc0 = bb[col], bc1 = bb[col + 1];
            #pragma unroll
            for (int h = 0; h < 2; h++) {
                int rl = wm * 32 + mf * 16 + lq + h * 8;
                int nc = min(n0 + rl, NN - 1);
                float dg = sdeg[rl];
                float s0, s1;
                if (hself) {
                    float2 sv = *(const float2*)&hself[nc * HH + col];
                    s0 = sv.x; s1 = sv.y;
                } else { s0 = bsl[col]; s1 = bsl[col + 1]; }
                float2 o;
                o.x = fmaxf(acc[mf][nf][2 * h]     + dg * bc0 + s0, 0.f);
                o.y = fmaxf(acc[mf][nf][2 * h + 1] + dg * bc1 + s1, 0.f);
                *(float2*)&stage[rl * OSTR + col] = o;
            }
        }
    }
    __syncthreads();
    bool emit16 = (l < 2);
    #pragma unroll
    for (int i = 0; i < 16; i++) {
        int idx = i * 128 + tid;
        int row = idx >> 5, c4 = idx & 31;
        int n = n0 + row;
        if (n < NN) {
            float4 v = *(const float4*)&stage[row * OSTR + c4 * 4];
            *(float4*)&hout[n * HH + c4 * 4] = v;
            if (emit16)
                *(uint2*)&g_hh[n * 64 + c4 * 2] = make_uint2(h2pk(v.x, v.y), h2pk(v.z, v.w));
        }
    }
}

// ---- mean pool ----
__global__ void __launch_bounds__(256) k_pool(const int* __restrict__ batch) {
    int g = blockIdx.x;
    int tid = threadIdx.x;
    int j = tid & 127, half = tid >> 7;
    int lo = lbound(batch, NN, g);
    int hi = lbound(batch, NN, g + 1);
    float a = 0.f, b = 0.f;
    int n = lo + half;
    for (; n + 3 < hi; n += 4) {
        a += g_h1[n * HH + j];
        b += g_h1[(n + 2) * HH + j];
    }
    for (; n < hi; n += 2) a += g_h1[n * HH + j];
    __shared__ float red[256];
    red[tid] = a + b;
    __syncthreads();
    if (half == 0) {
        float s = red[j] + red[j + 128];
        float c = (float)(hi - lo);
        g_pool[g * HH + j] = s / fmaxf(c, 1.f);
    }
}

// ---- head ----
__global__ void k_head(const float* __restrict__ lig, const float* __restrict__ poc,
                       const float* __restrict__ Wl, const float* __restrict__ bl,
                       const float* __restrict__ Wp, const float* __restrict__ bp,
                       const float* __restrict__ Wf, const float* __restrict__ bf,
                       const float* __restrict__ Wo, const float* __restrict__ bo,
                       float* __restrict__ out) {
    int g = blockIdx.x, j = threadIdx.x;
    __shared__ float f[3 * HH];
    __shared__ float o[HH];
    f[j] = g_pool[g * HH + j];
    float a = bl[j];
    #pragma unroll 4
    for (int k = 0; k < FLIG; k++) a += lig[g * FLIG + k] * Wl[k * HH + j];
    f[HH + j] = a;
    float b = bp[j];
    #pragma unroll 4
    for (int k = 0; k < FPOC; k++) b += poc[g * FPOC + k] * Wp[k * HH + j];
    f[2 * HH + j] = b;
    __syncthreads();
    float acc = bf[j];
    #pragma unroll 8
    for (int k = 0; k < 3 * HH; k++) acc += f[k] * Wf[k * HH + j];
    o[j] = acc * Wo[j];
    __syncthreads();
    for (int s = 64; s > 0; s >>= 1) {
        if (j < s) o[j] += o[j + s];
        __syncthreads();
    }
    if (j == 0) out[g] = o[0] + bo[0];
}

extern "C" void kernel_launch(void* const* d_in, const int* in_sizes, int n_in,
                              void* d_out, int out_size) {
    const float* x    = (const float*)d_in[0];
    const int*   ei   = (const int*)d_in[1];
    const float* ea   = (const float*)d_in[2];
    const int*   batch= (const int*)d_in[3];
    const float* lig  = (const float*)d_in[4];
    const float* poc  = (const float*)d_in[5];
    const float* W1m  = (const float*)d_in[6];
    const float* b1m  = (const float*)d_in[7];
    const float* W1e  = (const float*)d_in[8];
    const float* b1e  = (const float*)d_in[9];
    const float* W1s  = (const float*)d_in[10];
    const float* b1s  = (const float*)d_in[11];
    const float* Wkm  = (const float*)d_in[12];
    const float* bkm  = (const float*)d_in[13];
    const float* Wke  = (const float*)d_in[14];
    const float* bke  = (const float*)d_in[15];
    const float* Wl   = (const float*)d_in[16];
    const float* bl   = (const float*)d_in[17];
    const float* Wp   = (const float*)d_in[18];
    const float* bp   = (const float*)d_in[19];
    const float* Wf   = (const float*)d_in[20];
    const float* bf   = (const float*)d_in[21];
    const float* Wo   = (const float*)d_in[22];
    const float* bo   = (const float*)d_in[23];
    float* out = (float*)d_out;

    k_count  <<<(NN * (FN / 2) + 255) / 256, 256>>>(ei, x);             // 0 (covers xconv range)
    k_scan   <<<1, 1024>>>();                                           // 1
    k_fill   <<<(EE + 255) / 256, 256>>>(ei);                           // 2
    k_gather1<<<GBLK, 256>>>(ea);                                       // 3 (profiled)
    k_wconv  <<<(4 * WIMG + 255) / 256, 256>>>(W1m, W1s, W1e, Wkm, Wke);// 4
    k_gemm   <<<MBLK, 128>>>(-1, b1m, b1e, b1s);                        // 5
    for (int l = 0; l < 3; l++) {
        k_gatherL<<<GBLK, 256>>>(l);
        k_gemm   <<<MBLK, 128>>>(l, bkm + l * HH, bke + l * HH, nullptr);
    }
    k_pool <<<GG, 256>>>(batch);
    k_head <<<GG, HH>>>(lig, poc, Wl, bl, Wp, bp, Wf, bf, Wo, bo, out);
}